// round 1
// baseline (speedup 1.0000x reference)
#include <cuda_runtime.h>
#include <cstddef>

#define TN_ 64
#define MN_ 64
#define ROI_ 2048
#define SPA_ 4
#define WORD_ 300
#define INF_ 2352           // ROI+SPA+WORD (weight row stride)
#define INX_ 2052           // ROI+SPA (actual GEMM K)
#define H_ 512
#define D_ 256
#define LDR_ 556            // rel_w1 row stride (D+WORD)
#define NT_ (TN_*MN_)       // 4096 tokens

// ---------------- scratch (static device globals; no allocation) ------------
__device__ float g_X[NT_*INX_];       // concat(roi, spatial)
__device__ float g_h1[NT_*H_];        // shared hidden buffer (reused)
__device__ float g_fsb[NT_*D_];
__device__ float g_fob[NT_*D_];
__device__ float g_fs[NT_*D_];
__device__ float g_fo[NT_*D_];
__device__ float g_A[NT_*H_];         // fs @ (Wd W_rs)^T
__device__ float g_Bm[NT_*H_];        // fo @ (Wd W_ro)^T
__device__ float g_sbias[H_], g_obias[H_], g_rbias[H_];
__device__ float g_weffs[H_*D_], g_weffo[H_*D_];
__device__ float g_Ms[H_*D_], g_Mo[H_*D_];

// ---------------- small prep kernels ---------------------------------------

__global__ void concat_kernel(const float* __restrict__ roi,
                              const float* __restrict__ spa) {
    int idx = blockIdx.x * blockDim.x + threadIdx.x;
    if (idx >= NT_ * INX_) return;
    int r = idx / INX_;
    int c = idx - r * INX_;
    g_X[idx] = (c < ROI_) ? roi[r * ROI_ + c] : spa[r * SPA_ + (c - ROI_)];
}

// fold the broadcast word-embedding slice of each first-layer weight into a bias
__global__ void prep_bias(const float* __restrict__ subj_w1, const float* __restrict__ subj_b1,
                          const float* __restrict__ obj_w1,  const float* __restrict__ obj_b1,
                          const float* __restrict__ rel_w1,  const float* __restrict__ rel_b1,
                          const float* __restrict__ subj_emb,
                          const float* __restrict__ obj_emb,
                          const float* __restrict__ pred_emb) {
    int h = blockIdx.x * blockDim.x + threadIdx.x;
    if (h >= H_) return;
    float s = subj_b1[h], o = obj_b1[h], r = rel_b1[h];
    const float* sw = subj_w1 + (size_t)h * INF_ + INX_;
    const float* ow = obj_w1  + (size_t)h * INF_ + INX_;
    const float* rw = rel_w1  + (size_t)h * LDR_ + D_;
    for (int w = 0; w < WORD_; w++) {
        s += sw[w] * subj_emb[w];
        o += ow[w] * obj_emb[w];
        r += rw[w] * pred_emb[w];
    }
    g_sbias[h] = s; g_obias[h] = o; g_rbias[h] = r;
}

// concat([x,x]) @ W^T == x @ (W[:, :D] + W[:, D:])^T
__global__ void prep_weff(const float* __restrict__ fsw1,
                          const float* __restrict__ fow1) {
    int idx = blockIdx.x * blockDim.x + threadIdx.x;
    if (idx >= H_ * D_) return;
    int h = idx >> 8, k = idx & (D_ - 1);
    g_weffs[idx] = fsw1[h * (2*D_) + k] + fsw1[h * (2*D_) + D_ + k];
    g_weffo[idx] = fow1[h * (2*D_) + k] + fow1[h * (2*D_) + D_ + k];
}

// M_s = Wd @ W_rs,  M_o = Wd @ W_ro   (Wd = rel_w1[:, :D])  -> [H, D] each
__global__ void prep_M(const float* __restrict__ rel_w1,
                       const float* __restrict__ W_rs,
                       const float* __restrict__ W_ro) {
    int idx = blockIdx.x * blockDim.x + threadIdx.x;
    if (idx >= H_ * D_) return;
    int h = idx >> 8, k = idx & (D_ - 1);
    const float* wd = rel_w1 + (size_t)h * LDR_;
    float s = 0.f, o = 0.f;
    for (int d = 0; d < D_; d++) {
        float w = wd[d];
        s += w * W_rs[d * D_ + k];
        o += w * W_ro[d * D_ + k];
    }
    g_Ms[idx] = s; g_Mo[idx] = o;
}

// ---------------- generic SGEMM: C = act(A[M,K] @ B[N,K]^T + bias) ----------
// 64x64 tile, BK=16, 128 threads, 4x8 register micro-tile, float4 everywhere.

template <int RELU>
__global__ void __launch_bounds__(128) sgemm_abt(
    int M, int N, int K,
    const float* __restrict__ A, int lda,
    const float* __restrict__ B, int ldb,
    const float* __restrict__ bias,
    float* __restrict__ C, int ldc) {
    __shared__ float As[16][64];
    __shared__ float Bs[16][64];
    const int tid  = threadIdx.x;
    const int bm   = blockIdx.y * 64;
    const int bn   = blockIdx.x * 64;
    const int lrow = tid >> 2;          // 0..31
    const int lk4  = (tid & 3) << 2;    // 0,4,8,12
    const int ty   = tid >> 3;          // 0..15 -> m
    const int tx   = tid & 7;           // 0..7  -> n

    float acc[4][8];
#pragma unroll
    for (int i = 0; i < 4; i++)
#pragma unroll
        for (int j = 0; j < 8; j++) acc[i][j] = 0.f;

    for (int k0 = 0; k0 < K; k0 += 16) {
        const int gk = k0 + lk4;
        const bool ok = gk < K;          // K=2052 tail handled (K%4==0)
#pragma unroll
        for (int r = 0; r < 2; r++) {
            const int row = lrow + r * 32;
            float4 va = ok ? *(const float4*)(A + (size_t)(bm + row) * lda + gk)
                           : make_float4(0.f, 0.f, 0.f, 0.f);
            As[lk4 + 0][row] = va.x; As[lk4 + 1][row] = va.y;
            As[lk4 + 2][row] = va.z; As[lk4 + 3][row] = va.w;
            float4 vb = ok ? *(const float4*)(B + (size_t)(bn + row) * ldb + gk)
                           : make_float4(0.f, 0.f, 0.f, 0.f);
            Bs[lk4 + 0][row] = vb.x; Bs[lk4 + 1][row] = vb.y;
            Bs[lk4 + 2][row] = vb.z; Bs[lk4 + 3][row] = vb.w;
        }
        __syncthreads();
#pragma unroll
        for (int kk = 0; kk < 16; kk++) {
            float4 ra  = *(const float4*)&As[kk][ty * 4];
            float4 rb0 = *(const float4*)&Bs[kk][tx * 8];
            float4 rb1 = *(const float4*)&Bs[kk][tx * 8 + 4];
            float am[4] = {ra.x, ra.y, ra.z, ra.w};
            float bv[8] = {rb0.x, rb0.y, rb0.z, rb0.w, rb1.x, rb1.y, rb1.z, rb1.w};
#pragma unroll
            for (int i = 0; i < 4; i++)
#pragma unroll
                for (int j = 0; j < 8; j++) acc[i][j] += am[i] * bv[j];
        }
        __syncthreads();
    }

    const int n0 = bn + tx * 8;
#pragma unroll
    for (int i = 0; i < 4; i++) {
        const int m = bm + ty * 4 + i;
        float v[8];
#pragma unroll
        for (int j = 0; j < 8; j++) {
            float x = acc[i][j] + (bias ? bias[n0 + j] : 0.f);
            if (RELU) x = fmaxf(x, 0.f);
            v[j] = x;
        }
        float4* dst = (float4*)(C + (size_t)m * ldc + n0);
        dst[0] = make_float4(v[0], v[1], v[2], v[3]);
        dst[1] = make_float4(v[4], v[5], v[6], v[7]);
    }
}

// ---------------- fused pairwise final kernel -------------------------------
// out[ti, j, n] = relu(A[ti] - B[t*64+j] + rbias) @ rel_w2^T + rel_b2
// One block = one (t,i) row-group x 64-wide N tile; h-tile built in smem on the fly.

__global__ void __launch_bounds__(128) final_kernel(
    const float* __restrict__ Af,   // [NT, H]
    const float* __restrict__ Bf,   // [NT, H]
    const float* __restrict__ W2,   // rel_w2 [D, H]
    const float* __restrict__ hb,   // g_rbias [H]
    const float* __restrict__ b2,   // rel_b2 [D]
    float* __restrict__ out) {      // [NT, 64, D]
    __shared__ float Hs[16][64];
    __shared__ float Ws[16][64];
    const int tid  = threadIdx.x;
    const int ti   = blockIdx.y;        // t*64 + i
    const int t    = ti >> 6;
    const int bn   = blockIdx.x * 64;
    const int lrow = tid >> 2;
    const int lk4  = (tid & 3) << 2;
    const int ty   = tid >> 3;
    const int tx   = tid & 7;

    const float* arow  = Af + (size_t)ti * H_;
    const float* bbase = Bf + (size_t)t * 64 * H_;

    float acc[4][8];
#pragma unroll
    for (int i = 0; i < 4; i++)
#pragma unroll
        for (int j = 0; j < 8; j++) acc[i][j] = 0.f;

    for (int k0 = 0; k0 < H_; k0 += 16) {
        const int gk = k0 + lk4;
        const float4 va = *(const float4*)(arow + gk);
        const float4 vc = *(const float4*)(hb + gk);
#pragma unroll
        for (int r = 0; r < 2; r++) {
            const int row = lrow + r * 32;   // j index (Hs) / n-row (Ws)
            float4 vb = *(const float4*)(bbase + (size_t)row * H_ + gk);
            Hs[lk4 + 0][row] = fmaxf(va.x - vb.x + vc.x, 0.f);
            Hs[lk4 + 1][row] = fmaxf(va.y - vb.y + vc.y, 0.f);
            Hs[lk4 + 2][row] = fmaxf(va.z - vb.z + vc.z, 0.f);
            Hs[lk4 + 3][row] = fmaxf(va.w - vb.w + vc.w, 0.f);
            float4 vw = *(const float4*)(W2 + (size_t)(bn + row) * H_ + gk);
            Ws[lk4 + 0][row] = vw.x; Ws[lk4 + 1][row] = vw.y;
            Ws[lk4 + 2][row] = vw.z; Ws[lk4 + 3][row] = vw.w;
        }
        __syncthreads();
#pragma unroll
        for (int kk = 0; kk < 16; kk++) {
            float4 ra  = *(const float4*)&Hs[kk][ty * 4];
            float4 rb0 = *(const float4*)&Ws[kk][tx * 8];
            float4 rb1 = *(const float4*)&Ws[kk][tx * 8 + 4];
            float am[4] = {ra.x, ra.y, ra.z, ra.w};
            float bv[8] = {rb0.x, rb0.y, rb0.z, rb0.w, rb1.x, rb1.y, rb1.z, rb1.w};
#pragma unroll
            for (int i = 0; i < 4; i++)
#pragma unroll
                for (int j = 0; j < 8; j++) acc[i][j] += am[i] * bv[j];
        }
        __syncthreads();
    }

    const int n0 = bn + tx * 8;
#pragma unroll
    for (int i = 0; i < 4; i++) {
        const int j = ty * 4 + i;                       // pair's j index
        float v[8];
#pragma unroll
        for (int q = 0; q < 8; q++) v[q] = acc[i][q] + b2[n0 + q];
        float4* dst = (float4*)(out + ((size_t)ti * 64 + j) * D_ + n0);
        dst[0] = make_float4(v[0], v[1], v[2], v[3]);
        dst[1] = make_float4(v[4], v[5], v[6], v[7]);
    }
}

// ---------------- host orchestration ----------------------------------------

extern "C" void kernel_launch(void* const* d_in, const int* in_sizes, int n_in,
                              void* d_out, int out_size) {
    const float* roi      = (const float*)d_in[0];
    const float* spa      = (const float*)d_in[1];
    // d_in[2] = i3d_feats : unused by the reference
    const float* subj_emb = (const float*)d_in[3];
    const float* obj_emb  = (const float*)d_in[4];
    const float* pred_emb = (const float*)d_in[5];
    const float* subj_w1  = (const float*)d_in[6];
    const float* subj_b1  = (const float*)d_in[7];
    const float* subj_w2  = (const float*)d_in[8];
    const float* subj_b2  = (const float*)d_in[9];
    const float* obj_w1   = (const float*)d_in[10];
    const float* obj_b1   = (const float*)d_in[11];
    const float* obj_w2   = (const float*)d_in[12];
    const float* obj_b2   = (const float*)d_in[13];
    const float* fuse_s_w1= (const float*)d_in[14];
    const float* fuse_s_b1= (const float*)d_in[15];
    const float* fuse_s_w2= (const float*)d_in[16];
    const float* fuse_s_b2= (const float*)d_in[17];
    const float* fuse_o_w1= (const float*)d_in[18];
    const float* fuse_o_b1= (const float*)d_in[19];
    const float* fuse_o_w2= (const float*)d_in[20];
    const float* fuse_o_b2= (const float*)d_in[21];
    const float* W_rs     = (const float*)d_in[22];
    const float* W_ro     = (const float*)d_in[23];
    const float* rel_w1   = (const float*)d_in[24];
    const float* rel_b1   = (const float*)d_in[25];
    const float* rel_w2   = (const float*)d_in[26];
    const float* rel_b2   = (const float*)d_in[27];
    float* out = (float*)d_out;

    float *pX, *ph1, *pfsb, *pfob, *pfs, *pfo, *pA, *pB;
    float *psb, *pob, *prb, *pws, *pwo, *pMs, *pMo;
    cudaGetSymbolAddress((void**)&pX,  g_X);
    cudaGetSymbolAddress((void**)&ph1, g_h1);
    cudaGetSymbolAddress((void**)&pfsb,g_fsb);
    cudaGetSymbolAddress((void**)&pfob,g_fob);
    cudaGetSymbolAddress((void**)&pfs, g_fs);
    cudaGetSymbolAddress((void**)&pfo, g_fo);
    cudaGetSymbolAddress((void**)&pA,  g_A);
    cudaGetSymbolAddress((void**)&pB,  g_Bm);
    cudaGetSymbolAddress((void**)&psb, g_sbias);
    cudaGetSymbolAddress((void**)&pob, g_obias);
    cudaGetSymbolAddress((void**)&prb, g_rbias);
    cudaGetSymbolAddress((void**)&pws, g_weffs);
    cudaGetSymbolAddress((void**)&pwo, g_weffo);
    cudaGetSymbolAddress((void**)&pMs, g_Ms);
    cudaGetSymbolAddress((void**)&pMo, g_Mo);

    concat_kernel<<<(NT_*INX_ + 255) / 256, 256>>>(roi, spa);
    prep_bias<<<2, 256>>>(subj_w1, subj_b1, obj_w1, obj_b1, rel_w1, rel_b1,
                          subj_emb, obj_emb, pred_emb);
    prep_weff<<<(H_*D_ + 255) / 256, 256>>>(fuse_s_w1, fuse_o_w1);
    prep_M<<<(H_*D_ + 255) / 256, 256>>>(rel_w1, W_rs, W_ro);

    const dim3 blk(128);
    // subj branch: h1 = relu(X @ W1[:, :2052]^T + sbias); fs_base = h1 @ W2^T + b2
    sgemm_abt<1><<<dim3(H_/64, NT_/64), blk>>>(NT_, H_, INX_, pX, INX_, subj_w1, INF_, psb, ph1, H_);
    sgemm_abt<0><<<dim3(D_/64, NT_/64), blk>>>(NT_, D_, H_,   ph1, H_,  subj_w2, H_,  subj_b2, pfsb, D_);
    // obj branch
    sgemm_abt<1><<<dim3(H_/64, NT_/64), blk>>>(NT_, H_, INX_, pX, INX_, obj_w1, INF_, pob, ph1, H_);
    sgemm_abt<0><<<dim3(D_/64, NT_/64), blk>>>(NT_, D_, H_,   ph1, H_,  obj_w2, H_,  obj_b2, pfob, D_);
    // fuse subj: fs = mlp2(fs_base) with summed first-layer weight
    sgemm_abt<1><<<dim3(H_/64, NT_/64), blk>>>(NT_, H_, D_, pfsb, D_, pws, D_, fuse_s_b1, ph1, H_);
    sgemm_abt<0><<<dim3(D_/64, NT_/64), blk>>>(NT_, D_, H_, ph1, H_, fuse_s_w2, H_, fuse_s_b2, pfs, D_);
    // fuse obj
    sgemm_abt<1><<<dim3(H_/64, NT_/64), blk>>>(NT_, H_, D_, pfob, D_, pwo, D_, fuse_o_b1, ph1, H_);
    sgemm_abt<0><<<dim3(D_/64, NT_/64), blk>>>(NT_, D_, H_, ph1, H_, fuse_o_w2, H_, fuse_o_b2, pfo, D_);
    // projections folded with Wd: A = fs @ Ms^T, B = fo @ Mo^T
    sgemm_abt<0><<<dim3(H_/64, NT_/64), blk>>>(NT_, H_, D_, pfs, D_, pMs, D_, nullptr, pA, H_);
    sgemm_abt<0><<<dim3(H_/64, NT_/64), blk>>>(NT_, H_, D_, pfo, D_, pMo, D_, nullptr, pB, H_);
    // fused pairwise ReLU-GEMM epilogue -> 256 MB output
    final_kernel<<<dim3(D_/64, NT_), blk>>>(pA, pB, rel_w2, prb, rel_b2, out);
}

// round 2
// speedup vs baseline: 2.7240x; 2.7240x over previous
#include <cuda_runtime.h>
#include <cstddef>

#define TN_ 64
#define MN_ 64
#define ROI_ 2048
#define SPA_ 4
#define WORD_ 300
#define INF_ 2352           // ROI+SPA+WORD (weight row stride)
#define INX_ 2052           // ROI+SPA (actual GEMM K)
#define H_ 512
#define D_ 256
#define LDR_ 556            // rel_w1 row stride (D+WORD)
#define NT_ (TN_*MN_)       // 4096 tokens

// ---------------- scratch (static device globals; no allocation) ------------
__device__ float g_X[NT_*INX_];       // concat(roi, spatial)
__device__ float g_h1[NT_*H_];        // shared hidden buffer (reused)
__device__ float g_fsb[NT_*D_];
__device__ float g_fob[NT_*D_];
__device__ float g_fs[NT_*D_];
__device__ float g_fo[NT_*D_];
__device__ float g_A[NT_*H_];         // fs @ (Wd W_rs)^T
__device__ float g_Bm[NT_*H_];        // fo @ (Wd W_ro)^T
__device__ float g_sbias[H_], g_obias[H_], g_rbias[H_];
__device__ float g_weffs[H_*D_], g_weffo[H_*D_];
__device__ float g_Ms[H_*D_], g_Mo[H_*D_];

// ---------------- helpers ----------------------------------------------------

__device__ __forceinline__ unsigned f2tf(float x) {
    unsigned u;
    asm("cvt.rna.tf32.f32 %0, %1;" : "=r"(u) : "f"(x));
    return u;
}

__device__ __forceinline__ void mma_tf32(float* d, const unsigned* a, const unsigned* b) {
    asm volatile(
        "mma.sync.aligned.m16n8k8.row.col.f32.tf32.tf32.f32 "
        "{%0,%1,%2,%3}, {%4,%5,%6,%7}, {%8,%9}, {%0,%1,%2,%3};\n"
        : "+f"(d[0]), "+f"(d[1]), "+f"(d[2]), "+f"(d[3])
        : "r"(a[0]), "r"(a[1]), "r"(a[2]), "r"(a[3]),
          "r"(b[0]), "r"(b[1]));
}

// ---------------- small prep kernels ---------------------------------------

__global__ void concat_kernel(const float* __restrict__ roi,
                              const float* __restrict__ spa) {
    int idx = blockIdx.x * blockDim.x + threadIdx.x;
    if (idx >= NT_ * INX_) return;
    int r = idx / INX_;
    int c = idx - r * INX_;
    g_X[idx] = (c < ROI_) ? roi[r * ROI_ + c] : spa[r * SPA_ + (c - ROI_)];
}

__global__ void prep_bias(const float* __restrict__ subj_w1, const float* __restrict__ subj_b1,
                          const float* __restrict__ obj_w1,  const float* __restrict__ obj_b1,
                          const float* __restrict__ rel_w1,  const float* __restrict__ rel_b1,
                          const float* __restrict__ subj_emb,
                          const float* __restrict__ obj_emb,
                          const float* __restrict__ pred_emb) {
    int h = blockIdx.x * blockDim.x + threadIdx.x;
    if (h >= H_) return;
    float s = subj_b1[h], o = obj_b1[h], r = rel_b1[h];
    const float* sw = subj_w1 + (size_t)h * INF_ + INX_;
    const float* ow = obj_w1  + (size_t)h * INF_ + INX_;
    const float* rw = rel_w1  + (size_t)h * LDR_ + D_;
    for (int w = 0; w < WORD_; w++) {
        s += sw[w] * subj_emb[w];
        o += ow[w] * obj_emb[w];
        r += rw[w] * pred_emb[w];
    }
    g_sbias[h] = s; g_obias[h] = o; g_rbias[h] = r;
}

__global__ void prep_weff(const float* __restrict__ fsw1,
                          const float* __restrict__ fow1) {
    int idx = blockIdx.x * blockDim.x + threadIdx.x;
    if (idx >= H_ * D_) return;
    int h = idx >> 8, k = idx & (D_ - 1);
    g_weffs[idx] = fsw1[h * (2*D_) + k] + fsw1[h * (2*D_) + D_ + k];
    g_weffo[idx] = fow1[h * (2*D_) + k] + fow1[h * (2*D_) + D_ + k];
}

__global__ void prep_M(const float* __restrict__ rel_w1,
                       const float* __restrict__ W_rs,
                       const float* __restrict__ W_ro) {
    int idx = blockIdx.x * blockDim.x + threadIdx.x;
    if (idx >= H_ * D_) return;
    int h = idx >> 8, k = idx & (D_ - 1);
    const float* wd = rel_w1 + (size_t)h * LDR_;
    float s = 0.f, o = 0.f;
    for (int d = 0; d < D_; d++) {
        float w = wd[d];
        s += w * W_rs[d * D_ + k];
        o += w * W_ro[d * D_ + k];
    }
    g_Ms[idx] = s; g_Mo[idx] = o;
}

// ---------------- fp32 SIMT SGEMM (small layers): C = act(A@B^T + bias) -----

template <int RELU>
__global__ void __launch_bounds__(128) sgemm_abt(
    int M, int N, int K,
    const float* __restrict__ A, int lda,
    const float* __restrict__ B, int ldb,
    const float* __restrict__ bias,
    float* __restrict__ C, int ldc) {
    __shared__ float As[16][64];
    __shared__ float Bs[16][64];
    const int tid  = threadIdx.x;
    const int bm   = blockIdx.y * 64;
    const int bn   = blockIdx.x * 64;
    const int lrow = tid >> 2;
    const int lk4  = (tid & 3) << 2;
    const int ty   = tid >> 3;
    const int tx   = tid & 7;

    float acc[4][8];
#pragma unroll
    for (int i = 0; i < 4; i++)
#pragma unroll
        for (int j = 0; j < 8; j++) acc[i][j] = 0.f;

    for (int k0 = 0; k0 < K; k0 += 16) {
        const int gk = k0 + lk4;
        const bool ok = gk < K;
#pragma unroll
        for (int r = 0; r < 2; r++) {
            const int row = lrow + r * 32;
            float4 va = ok ? *(const float4*)(A + (size_t)(bm + row) * lda + gk)
                           : make_float4(0.f, 0.f, 0.f, 0.f);
            As[lk4 + 0][row] = va.x; As[lk4 + 1][row] = va.y;
            As[lk4 + 2][row] = va.z; As[lk4 + 3][row] = va.w;
            float4 vb = ok ? *(const float4*)(B + (size_t)(bn + row) * ldb + gk)
                           : make_float4(0.f, 0.f, 0.f, 0.f);
            Bs[lk4 + 0][row] = vb.x; Bs[lk4 + 1][row] = vb.y;
            Bs[lk4 + 2][row] = vb.z; Bs[lk4 + 3][row] = vb.w;
        }
        __syncthreads();
#pragma unroll
        for (int kk = 0; kk < 16; kk++) {
            float4 ra  = *(const float4*)&As[kk][ty * 4];
            float4 rb0 = *(const float4*)&Bs[kk][tx * 8];
            float4 rb1 = *(const float4*)&Bs[kk][tx * 8 + 4];
            float am[4] = {ra.x, ra.y, ra.z, ra.w};
            float bv[8] = {rb0.x, rb0.y, rb0.z, rb0.w, rb1.x, rb1.y, rb1.z, rb1.w};
#pragma unroll
            for (int i = 0; i < 4; i++)
#pragma unroll
                for (int j = 0; j < 8; j++) acc[i][j] += am[i] * bv[j];
        }
        __syncthreads();
    }

    const int n0 = bn + tx * 8;
#pragma unroll
    for (int i = 0; i < 4; i++) {
        const int m = bm + ty * 4 + i;
        float v[8];
#pragma unroll
        for (int j = 0; j < 8; j++) {
            float x = acc[i][j] + (bias ? bias[n0 + j] : 0.f);
            if (RELU) x = fmaxf(x, 0.f);
            v[j] = x;
        }
        float4* dst = (float4*)(C + (size_t)m * ldc + n0);
        dst[0] = make_float4(v[0], v[1], v[2], v[3]);
        dst[1] = make_float4(v[4], v[5], v[6], v[7]);
    }
}

// ---------------- tf32 tensor-core GEMM: C = act(A[M,K] @ B[N,K]^T + bias) ---
// 256 threads, block tile 128x128, BK=32, warp tile 32x64 (2 mfrag x 8 nfrag).
// Requires M%128==0, N%128==0, K%4==0 (zero-padded to K%32 inside).

template <int RELU>
__global__ void __launch_bounds__(256, 2) gemm_tc(
    int M, int N, int K,
    const float* __restrict__ A, int lda,
    const float* __restrict__ B, int ldb,
    const float* __restrict__ bias,
    float* __restrict__ C, int ldc) {
    __shared__ unsigned As[128][36];
    __shared__ unsigned Bs[128][36];
    const int tid  = threadIdx.x;
    const int lane = tid & 31;
    const int warp = tid >> 5;
    const int wm   = warp >> 1;     // 0..3
    const int wn   = warp & 1;      // 0..1
    const int bm   = blockIdx.y * 128;
    const int bn   = blockIdx.x * 128;
    const int lp   = tid >> 1;      // tile row 0..127
    const int lk   = (tid & 1) * 16;

    const float* arow = A + (size_t)(bm + lp) * lda;
    const float* brow = B + (size_t)(bn + lp) * ldb;

    float acc[2][8][4];
#pragma unroll
    for (int i = 0; i < 2; i++)
#pragma unroll
        for (int j = 0; j < 8; j++)
#pragma unroll
            for (int q = 0; q < 4; q++) acc[i][j][q] = 0.f;

    for (int k0 = 0; k0 < K; k0 += 32) {
#pragma unroll
        for (int q = 0; q < 4; q++) {
            const int k = k0 + lk + q * 4;
            const bool ok = k < K;
            float4 a4 = ok ? *(const float4*)(arow + k) : make_float4(0.f,0.f,0.f,0.f);
            float4 b4 = ok ? *(const float4*)(brow + k) : make_float4(0.f,0.f,0.f,0.f);
            const int kc = lk + q * 4;
            As[lp][kc+0] = f2tf(a4.x); As[lp][kc+1] = f2tf(a4.y);
            As[lp][kc+2] = f2tf(a4.z); As[lp][kc+3] = f2tf(a4.w);
            Bs[lp][kc+0] = f2tf(b4.x); Bs[lp][kc+1] = f2tf(b4.y);
            Bs[lp][kc+2] = f2tf(b4.z); Bs[lp][kc+3] = f2tf(b4.w);
        }
        __syncthreads();
#pragma unroll
        for (int ks = 0; ks < 4; ks++) {
            const int kb = ks * 8;
            unsigned af[2][4], bf[8][2];
#pragma unroll
            for (int mf = 0; mf < 2; mf++) {
                const int r = wm * 32 + mf * 16 + (lane >> 2);
                af[mf][0] = As[r    ][kb + (lane & 3)];
                af[mf][1] = As[r + 8][kb + (lane & 3)];
                af[mf][2] = As[r    ][kb + (lane & 3) + 4];
                af[mf][3] = As[r + 8][kb + (lane & 3) + 4];
            }
#pragma unroll
            for (int nf = 0; nf < 8; nf++) {
                const int n = wn * 64 + nf * 8 + (lane >> 2);
                bf[nf][0] = Bs[n][kb + (lane & 3)];
                bf[nf][1] = Bs[n][kb + (lane & 3) + 4];
            }
#pragma unroll
            for (int mf = 0; mf < 2; mf++)
#pragma unroll
                for (int nf = 0; nf < 8; nf++)
                    mma_tf32(acc[mf][nf], af[mf], bf[nf]);
        }
        __syncthreads();
    }

#pragma unroll
    for (int mf = 0; mf < 2; mf++) {
        const int r0 = bm + wm * 32 + mf * 16 + (lane >> 2);
#pragma unroll
        for (int nf = 0; nf < 8; nf++) {
            const int c0 = bn + wn * 64 + nf * 8 + 2 * (lane & 3);
            const float bv0 = bias ? bias[c0]     : 0.f;
            const float bv1 = bias ? bias[c0 + 1] : 0.f;
            float x0 = acc[mf][nf][0] + bv0, x1 = acc[mf][nf][1] + bv1;
            float x2 = acc[mf][nf][2] + bv0, x3 = acc[mf][nf][3] + bv1;
            if (RELU) { x0 = fmaxf(x0,0.f); x1 = fmaxf(x1,0.f);
                        x2 = fmaxf(x2,0.f); x3 = fmaxf(x3,0.f); }
            *(float2*)(C + (size_t)r0       * ldc + c0) = make_float2(x0, x1);
            *(float2*)(C + (size_t)(r0 + 8) * ldc + c0) = make_float2(x2, x3);
        }
    }
}

// ---------------- fused pairwise final kernel (tf32 tensor cores) ------------
// out[P, n] = relu(A[ti] - B[t*64+j] + rbias) @ rel_w2^T + rel_b2,
// P = ti*64 + j.  Block: 128 pairs (2 i's x 64 j) x 128 N-cols.

__global__ void __launch_bounds__(256, 2) final_tc(
    const float* __restrict__ Af,   // [NT, H]
    const float* __restrict__ Bf,   // [NT, H]
    const float* __restrict__ W2,   // rel_w2 [D, H]
    const float* __restrict__ hb,   // g_rbias [H]
    const float* __restrict__ b2,   // rel_b2 [D]
    float* __restrict__ out) {      // [NT*64, D]
    __shared__ unsigned Hs[128][36];
    __shared__ unsigned Ws[128][36];
    const int tid  = threadIdx.x;
    const int lane = tid & 31;
    const int warp = tid >> 5;
    const int wm   = warp >> 1;
    const int wn   = warp & 1;
    const int by   = blockIdx.y;           // pair block: pairs [by*128, by*128+128)
    const int bn   = blockIdx.x * 128;
    const int lp   = tid >> 1;             // 0..127 pair-row in tile
    const int lk   = (tid & 1) * 16;

    const int j       = lp & 63;
    const int i_local = lp >> 6;           // 0..1
    const int ti      = by * 2 + i_local;
    const int t       = ti >> 6;

    const float* arow = Af + (size_t)ti * H_;
    const float* brow = Bf + ((size_t)t * 64 + j) * H_;
    const float* wrow = W2 + (size_t)(bn + lp) * H_;

    float acc[2][8][4];
#pragma unroll
    for (int i = 0; i < 2; i++)
#pragma unroll
        for (int q = 0; q < 8; q++)
#pragma unroll
            for (int z = 0; z < 4; z++) acc[i][q][z] = 0.f;

    for (int k0 = 0; k0 < H_; k0 += 32) {
#pragma unroll
        for (int q = 0; q < 4; q++) {
            const int k  = k0 + lk + q * 4;
            const int kc = lk + q * 4;
            float4 a4 = *(const float4*)(arow + k);
            float4 b4 = *(const float4*)(brow + k);
            float4 c4 = *(const float4*)(hb + k);
            Hs[lp][kc+0] = f2tf(fmaxf(a4.x - b4.x + c4.x, 0.f));
            Hs[lp][kc+1] = f2tf(fmaxf(a4.y - b4.y + c4.y, 0.f));
            Hs[lp][kc+2] = f2tf(fmaxf(a4.z - b4.z + c4.z, 0.f));
            Hs[lp][kc+3] = f2tf(fmaxf(a4.w - b4.w + c4.w, 0.f));
            float4 w4 = *(const float4*)(wrow + k);
            Ws[lp][kc+0] = f2tf(w4.x); Ws[lp][kc+1] = f2tf(w4.y);
            Ws[lp][kc+2] = f2tf(w4.z); Ws[lp][kc+3] = f2tf(w4.w);
        }
        __syncthreads();
#pragma unroll
        for (int ks = 0; ks < 4; ks++) {
            const int kb = ks * 8;
            unsigned af[2][4], bf[8][2];
#pragma unroll
            for (int mf = 0; mf < 2; mf++) {
                const int r = wm * 32 + mf * 16 + (lane >> 2);
                af[mf][0] = Hs[r    ][kb + (lane & 3)];
                af[mf][1] = Hs[r + 8][kb + (lane & 3)];
                af[mf][2] = Hs[r    ][kb + (lane & 3) + 4];
                af[mf][3] = Hs[r + 8][kb + (lane & 3) + 4];
            }
#pragma unroll
            for (int nf = 0; nf < 8; nf++) {
                const int n = wn * 64 + nf * 8 + (lane >> 2);
                bf[nf][0] = Ws[n][kb + (lane & 3)];
                bf[nf][1] = Ws[n][kb + (lane & 3) + 4];
            }
#pragma unroll
            for (int mf = 0; mf < 2; mf++)
#pragma unroll
                for (int nf = 0; nf < 8; nf++)
                    mma_tf32(acc[mf][nf], af[mf], bf[nf]);
        }
        __syncthreads();
    }

#pragma unroll
    for (int mf = 0; mf < 2; mf++) {
        const int P0 = by * 128 + wm * 32 + mf * 16 + (lane >> 2);
#pragma unroll
        for (int nf = 0; nf < 8; nf++) {
            const int c0 = bn + wn * 64 + nf * 8 + 2 * (lane & 3);
            const float bv0 = b2[c0], bv1 = b2[c0 + 1];
            *(float2*)(out + (size_t)P0       * D_ + c0) =
                make_float2(acc[mf][nf][0] + bv0, acc[mf][nf][1] + bv1);
            *(float2*)(out + (size_t)(P0 + 8) * D_ + c0) =
                make_float2(acc[mf][nf][2] + bv0, acc[mf][nf][3] + bv1);
        }
    }
}

// ---------------- host orchestration ----------------------------------------

extern "C" void kernel_launch(void* const* d_in, const int* in_sizes, int n_in,
                              void* d_out, int out_size) {
    const float* roi      = (const float*)d_in[0];
    const float* spa      = (const float*)d_in[1];
    const float* subj_emb = (const float*)d_in[3];
    const float* obj_emb  = (const float*)d_in[4];
    const float* pred_emb = (const float*)d_in[5];
    const float* subj_w1  = (const float*)d_in[6];
    const float* subj_b1  = (const float*)d_in[7];
    const float* subj_w2  = (const float*)d_in[8];
    const float* subj_b2  = (const float*)d_in[9];
    const float* obj_w1   = (const float*)d_in[10];
    const float* obj_b1   = (const float*)d_in[11];
    const float* obj_w2   = (const float*)d_in[12];
    const float* obj_b2   = (const float*)d_in[13];
    const float* fuse_s_w1= (const float*)d_in[14];
    const float* fuse_s_b1= (const float*)d_in[15];
    const float* fuse_s_w2= (const float*)d_in[16];
    const float* fuse_s_b2= (const float*)d_in[17];
    const float* fuse_o_w1= (const float*)d_in[18];
    const float* fuse_o_b1= (const float*)d_in[19];
    const float* fuse_o_w2= (const float*)d_in[20];
    const float* fuse_o_b2= (const float*)d_in[21];
    const float* W_rs     = (const float*)d_in[22];
    const float* W_ro     = (const float*)d_in[23];
    const float* rel_w1   = (const float*)d_in[24];
    const float* rel_b1   = (const float*)d_in[25];
    const float* rel_w2   = (const float*)d_in[26];
    const float* rel_b2   = (const float*)d_in[27];
    float* out = (float*)d_out;

    float *pX, *ph1, *pfsb, *pfob, *pfs, *pfo, *pA, *pB;
    float *psb, *pob, *prb, *pws, *pwo, *pMs, *pMo;
    cudaGetSymbolAddress((void**)&pX,  g_X);
    cudaGetSymbolAddress((void**)&ph1, g_h1);
    cudaGetSymbolAddress((void**)&pfsb,g_fsb);
    cudaGetSymbolAddress((void**)&pfob,g_fob);
    cudaGetSymbolAddress((void**)&pfs, g_fs);
    cudaGetSymbolAddress((void**)&pfo, g_fo);
    cudaGetSymbolAddress((void**)&pA,  g_A);
    cudaGetSymbolAddress((void**)&pB,  g_Bm);
    cudaGetSymbolAddress((void**)&psb, g_sbias);
    cudaGetSymbolAddress((void**)&pob, g_obias);
    cudaGetSymbolAddress((void**)&prb, g_rbias);
    cudaGetSymbolAddress((void**)&pws, g_weffs);
    cudaGetSymbolAddress((void**)&pwo, g_weffo);
    cudaGetSymbolAddress((void**)&pMs, g_Ms);
    cudaGetSymbolAddress((void**)&pMo, g_Mo);

    concat_kernel<<<(NT_*INX_ + 255) / 256, 256>>>(roi, spa);
    prep_bias<<<2, 256>>>(subj_w1, subj_b1, obj_w1, obj_b1, rel_w1, rel_b1,
                          subj_emb, obj_emb, pred_emb);
    prep_weff<<<(H_*D_ + 255) / 256, 256>>>(fuse_s_w1, fuse_o_w1);
    prep_M<<<(H_*D_ + 255) / 256, 256>>>(rel_w1, W_rs, W_ro);

    const dim3 blk(128);
    const dim3 tblk(256);
    // subj branch L1 (tf32 TC): h1 = relu(X @ W1[:, :2052]^T + sbias)
    gemm_tc<1><<<dim3(H_/128, NT_/128), tblk>>>(NT_, H_, INX_, pX, INX_, subj_w1, INF_, psb, ph1, H_);
    sgemm_abt<0><<<dim3(D_/64, NT_/64), blk>>>(NT_, D_, H_,   ph1, H_,  subj_w2, H_,  subj_b2, pfsb, D_);
    // obj branch
    gemm_tc<1><<<dim3(H_/128, NT_/128), tblk>>>(NT_, H_, INX_, pX, INX_, obj_w1, INF_, pob, ph1, H_);
    sgemm_abt<0><<<dim3(D_/64, NT_/64), blk>>>(NT_, D_, H_,   ph1, H_,  obj_w2, H_,  obj_b2, pfob, D_);
    // fuse subj
    sgemm_abt<1><<<dim3(H_/64, NT_/64), blk>>>(NT_, H_, D_, pfsb, D_, pws, D_, fuse_s_b1, ph1, H_);
    sgemm_abt<0><<<dim3(D_/64, NT_/64), blk>>>(NT_, D_, H_, ph1, H_, fuse_s_w2, H_, fuse_s_b2, pfs, D_);
    // fuse obj
    sgemm_abt<1><<<dim3(H_/64, NT_/64), blk>>>(NT_, H_, D_, pfob, D_, pwo, D_, fuse_o_b1, ph1, H_);
    sgemm_abt<0><<<dim3(D_/64, NT_/64), blk>>>(NT_, D_, H_, ph1, H_, fuse_o_w2, H_, fuse_o_b2, pfo, D_);
    // projections folded with Wd
    sgemm_abt<0><<<dim3(H_/64, NT_/64), blk>>>(NT_, H_, D_, pfs, D_, pMs, D_, nullptr, pA, H_);
    sgemm_abt<0><<<dim3(H_/64, NT_/64), blk>>>(NT_, H_, D_, pfo, D_, pMo, D_, nullptr, pB, H_);
    // fused pairwise ReLU-GEMM epilogue (tf32 TC) -> 256 MB output
    final_tc<<<dim3(D_/128, NT_*64/128), tblk>>>(pA, pB, rel_w2, prb, rel_b2, out);
}

// round 3
// speedup vs baseline: 3.0158x; 1.1071x over previous
#include <cuda_runtime.h>
#include <cstddef>

#define TN_ 64
#define MN_ 64
#define ROI_ 2048
#define SPA_ 4
#define WORD_ 300
#define INF_ 2352           // ROI+SPA+WORD (weight row stride)
#define INX_ 2052           // ROI+SPA (actual GEMM K)
#define H_ 512
#define D_ 256
#define LDR_ 556            // rel_w1 row stride (D+WORD)
#define NT_ (TN_*MN_)       // 4096 tokens

// ---------------- scratch (static device globals; no allocation) ------------
__device__ float g_X[NT_*INX_];       // concat(roi, spatial)
__device__ float g_h1[NT_*H_];        // shared hidden buffer (reused)
__device__ float g_fsb[NT_*D_];
__device__ float g_fob[NT_*D_];
__device__ float g_fs[NT_*D_];
__device__ float g_fo[NT_*D_];
__device__ float g_A[NT_*H_];         // fs @ (Wd W_rs)^T
__device__ float g_Bm[NT_*H_];        // fo @ (Wd W_ro)^T
__device__ float g_sbias[H_], g_obias[H_], g_rbias[H_];
__device__ float g_weffs[H_*D_], g_weffo[H_*D_];
__device__ float g_Ms[H_*D_], g_Mo[H_*D_];

// ---------------- helpers ----------------------------------------------------

__device__ __forceinline__ unsigned f2tf(float x) {
    unsigned u;
    asm("cvt.rna.tf32.f32 %0, %1;" : "=r"(u) : "f"(x));
    return u;
}

__device__ __forceinline__ void mma_tf32(float* d, const unsigned* a, const unsigned* b) {
    asm volatile(
        "mma.sync.aligned.m16n8k8.row.col.f32.tf32.tf32.f32 "
        "{%0,%1,%2,%3}, {%4,%5,%6,%7}, {%8,%9}, {%0,%1,%2,%3};\n"
        : "+f"(d[0]), "+f"(d[1]), "+f"(d[2]), "+f"(d[3])
        : "r"(a[0]), "r"(a[1]), "r"(a[2]), "r"(a[3]),
          "r"(b[0]), "r"(b[1]));
}

// ---------------- small prep kernels ---------------------------------------

__global__ void concat_kernel(const float* __restrict__ roi,
                              const float* __restrict__ spa) {
    int idx = blockIdx.x * blockDim.x + threadIdx.x;
    if (idx >= NT_ * INX_) return;
    int r = idx / INX_;
    int c = idx - r * INX_;
    g_X[idx] = (c < ROI_) ? roi[r * ROI_ + c] : spa[r * SPA_ + (c - ROI_)];
}

__global__ void prep_bias(const float* __restrict__ subj_w1, const float* __restrict__ subj_b1,
                          const float* __restrict__ obj_w1,  const float* __restrict__ obj_b1,
                          const float* __restrict__ rel_w1,  const float* __restrict__ rel_b1,
                          const float* __restrict__ subj_emb,
                          const float* __restrict__ obj_emb,
                          const float* __restrict__ pred_emb) {
    int h = blockIdx.x * blockDim.x + threadIdx.x;
    if (h >= H_) return;
    float s = subj_b1[h], o = obj_b1[h], r = rel_b1[h];
    const float* sw = subj_w1 + (size_t)h * INF_ + INX_;
    const float* ow = obj_w1  + (size_t)h * INF_ + INX_;
    const float* rw = rel_w1  + (size_t)h * LDR_ + D_;
    for (int w = 0; w < WORD_; w++) {
        s += sw[w] * subj_emb[w];
        o += ow[w] * obj_emb[w];
        r += rw[w] * pred_emb[w];
    }
    g_sbias[h] = s; g_obias[h] = o; g_rbias[h] = r;
}

__global__ void prep_weff(const float* __restrict__ fsw1,
                          const float* __restrict__ fow1) {
    int idx = blockIdx.x * blockDim.x + threadIdx.x;
    if (idx >= H_ * D_) return;
    int h = idx >> 8, k = idx & (D_ - 1);
    g_weffs[idx] = fsw1[h * (2*D_) + k] + fsw1[h * (2*D_) + D_ + k];
    g_weffo[idx] = fow1[h * (2*D_) + k] + fow1[h * (2*D_) + D_ + k];
}

__global__ void prep_M(const float* __restrict__ rel_w1,
                       const float* __restrict__ W_rs,
                       const float* __restrict__ W_ro) {
    int idx = blockIdx.x * blockDim.x + threadIdx.x;
    if (idx >= H_ * D_) return;
    int h = idx >> 8, k = idx & (D_ - 1);
    const float* wd = rel_w1 + (size_t)h * LDR_;
    float s = 0.f, o = 0.f;
    for (int d = 0; d < D_; d++) {
        float w = wd[d];
        s += w * W_rs[d * D_ + k];
        o += w * W_ro[d * D_ + k];
    }
    g_Ms[idx] = s; g_Mo[idx] = o;
}

// ---------------- tf32 tensor-core GEMM: C = act(A[M,K] @ B[N,K]^T + bias) ---
// 256 threads, block tile 128x128, BK=32, warp tile 32x64 (2 mfrag x 8 nfrag).
// Requires M%128==0, N%128==0, K%4==0 (zero-padded to K%32 inside).

template <int RELU>
__global__ void __launch_bounds__(256, 2) gemm_tc(
    int M, int N, int K,
    const float* __restrict__ A, int lda,
    const float* __restrict__ B, int ldb,
    const float* __restrict__ bias,
    float* __restrict__ C, int ldc) {
    __shared__ unsigned As[128][36];
    __shared__ unsigned Bs[128][36];
    const int tid  = threadIdx.x;
    const int lane = tid & 31;
    const int warp = tid >> 5;
    const int wm   = warp >> 1;     // 0..3
    const int wn   = warp & 1;      // 0..1
    const int bm   = blockIdx.y * 128;
    const int bn   = blockIdx.x * 128;
    const int lp   = tid >> 1;      // tile row 0..127
    const int lk   = (tid & 1) * 16;

    const float* arow = A + (size_t)(bm + lp) * lda;
    const float* brow = B + (size_t)(bn + lp) * ldb;

    float acc[2][8][4];
#pragma unroll
    for (int i = 0; i < 2; i++)
#pragma unroll
        for (int j = 0; j < 8; j++)
#pragma unroll
            for (int q = 0; q < 4; q++) acc[i][j][q] = 0.f;

    for (int k0 = 0; k0 < K; k0 += 32) {
#pragma unroll
        for (int q = 0; q < 4; q++) {
            const int k = k0 + lk + q * 4;
            const bool ok = k < K;
            float4 a4 = ok ? *(const float4*)(arow + k) : make_float4(0.f,0.f,0.f,0.f);
            float4 b4 = ok ? *(const float4*)(brow + k) : make_float4(0.f,0.f,0.f,0.f);
            const int kc = lk + q * 4;
            As[lp][kc+0] = f2tf(a4.x); As[lp][kc+1] = f2tf(a4.y);
            As[lp][kc+2] = f2tf(a4.z); As[lp][kc+3] = f2tf(a4.w);
            Bs[lp][kc+0] = f2tf(b4.x); Bs[lp][kc+1] = f2tf(b4.y);
            Bs[lp][kc+2] = f2tf(b4.z); Bs[lp][kc+3] = f2tf(b4.w);
        }
        __syncthreads();
#pragma unroll
        for (int ks = 0; ks < 4; ks++) {
            const int kb = ks * 8;
            unsigned af[2][4], bf[8][2];
#pragma unroll
            for (int mf = 0; mf < 2; mf++) {
                const int r = wm * 32 + mf * 16 + (lane >> 2);
                af[mf][0] = As[r    ][kb + (lane & 3)];
                af[mf][1] = As[r + 8][kb + (lane & 3)];
                af[mf][2] = As[r    ][kb + (lane & 3) + 4];
                af[mf][3] = As[r + 8][kb + (lane & 3) + 4];
            }
#pragma unroll
            for (int nf = 0; nf < 8; nf++) {
                const int n = wn * 64 + nf * 8 + (lane >> 2);
                bf[nf][0] = Bs[n][kb + (lane & 3)];
                bf[nf][1] = Bs[n][kb + (lane & 3) + 4];
            }
#pragma unroll
            for (int mf = 0; mf < 2; mf++)
#pragma unroll
                for (int nf = 0; nf < 8; nf++)
                    mma_tf32(acc[mf][nf], af[mf], bf[nf]);
        }
        __syncthreads();
    }

#pragma unroll
    for (int mf = 0; mf < 2; mf++) {
        const int r0 = bm + wm * 32 + mf * 16 + (lane >> 2);
#pragma unroll
        for (int nf = 0; nf < 8; nf++) {
            const int c0 = bn + wn * 64 + nf * 8 + 2 * (lane & 3);
            const float bv0 = bias ? bias[c0]     : 0.f;
            const float bv1 = bias ? bias[c0 + 1] : 0.f;
            float x0 = acc[mf][nf][0] + bv0, x1 = acc[mf][nf][1] + bv1;
            float x2 = acc[mf][nf][2] + bv0, x3 = acc[mf][nf][3] + bv1;
            if (RELU) { x0 = fmaxf(x0,0.f); x1 = fmaxf(x1,0.f);
                        x2 = fmaxf(x2,0.f); x3 = fmaxf(x3,0.f); }
            *(float2*)(C + (size_t)r0       * ldc + c0) = make_float2(x0, x1);
            *(float2*)(C + (size_t)(r0 + 8) * ldc + c0) = make_float2(x2, x3);
        }
    }
}

// ---------------- tf32x2 split-precision TC GEMM (near-fp32 accuracy) --------
// C = act(A[M,K] @ B[N,K]^T + bias).  x = hi + lo; acc += hi*hi + hi*lo + lo*hi.
// Tile 128x64, BK=16, 256 threads, warp tile 32x32 (2 mfrag x 4 nfrag).
// Requires M%128==0, N%64==0, K%16==0.

template <int RELU>
__global__ void __launch_bounds__(256, 2) gemm_tcx2(
    int M, int N, int K,
    const float* __restrict__ A, int lda,
    const float* __restrict__ B, int ldb,
    const float* __restrict__ bias,
    float* __restrict__ C, int ldc) {
    __shared__ unsigned Ash[128][20], Asl[128][20];
    __shared__ unsigned Bsh[64][20],  Bsl[64][20];
    const int tid  = threadIdx.x;
    const int lane = tid & 31;
    const int warp = tid >> 5;
    const int wm   = warp >> 1;     // 0..3
    const int wn   = warp & 1;      // 0..1
    const int bm   = blockIdx.y * 128;
    const int bn   = blockIdx.x * 64;
    const int la   = tid >> 1;           // A row 0..127
    const int lak  = (tid & 1) * 8;      // A col base
    const int lb   = tid >> 2;           // B row 0..63
    const int lbk  = (tid & 3) * 4;      // B col base

    const float* arow = A + (size_t)(bm + la) * lda;
    const float* brow = B + (size_t)(bn + lb) * ldb;

    float acc[2][4][4];
#pragma unroll
    for (int i = 0; i < 2; i++)
#pragma unroll
        for (int j = 0; j < 4; j++)
#pragma unroll
            for (int q = 0; q < 4; q++) acc[i][j][q] = 0.f;

    for (int k0 = 0; k0 < K; k0 += 16) {
#pragma unroll
        for (int q = 0; q < 2; q++) {
            float4 a4 = *(const float4*)(arow + k0 + lak + q * 4);
            const int kc = lak + q * 4;
            float av[4] = {a4.x, a4.y, a4.z, a4.w};
#pragma unroll
            for (int c = 0; c < 4; c++) {
                unsigned hi = f2tf(av[c]);
                Ash[la][kc + c] = hi;
                Asl[la][kc + c] = f2tf(av[c] - __uint_as_float(hi));
            }
        }
        {
            float4 b4 = *(const float4*)(brow + k0 + lbk);
            float bv[4] = {b4.x, b4.y, b4.z, b4.w};
#pragma unroll
            for (int c = 0; c < 4; c++) {
                unsigned hi = f2tf(bv[c]);
                Bsh[lb][lbk + c] = hi;
                Bsl[lb][lbk + c] = f2tf(bv[c] - __uint_as_float(hi));
            }
        }
        __syncthreads();
#pragma unroll
        for (int ks = 0; ks < 2; ks++) {
            const int kb = ks * 8;
            unsigned afh[2][4], afl[2][4], bfh[4][2], bfl[4][2];
#pragma unroll
            for (int mf = 0; mf < 2; mf++) {
                const int r = wm * 32 + mf * 16 + (lane >> 2);
                afh[mf][0] = Ash[r    ][kb + (lane & 3)];
                afh[mf][1] = Ash[r + 8][kb + (lane & 3)];
                afh[mf][2] = Ash[r    ][kb + (lane & 3) + 4];
                afh[mf][3] = Ash[r + 8][kb + (lane & 3) + 4];
                afl[mf][0] = Asl[r    ][kb + (lane & 3)];
                afl[mf][1] = Asl[r + 8][kb + (lane & 3)];
                afl[mf][2] = Asl[r    ][kb + (lane & 3) + 4];
                afl[mf][3] = Asl[r + 8][kb + (lane & 3) + 4];
            }
#pragma unroll
            for (int nf = 0; nf < 4; nf++) {
                const int n = wn * 32 + nf * 8 + (lane >> 2);
                bfh[nf][0] = Bsh[n][kb + (lane & 3)];
                bfh[nf][1] = Bsh[n][kb + (lane & 3) + 4];
                bfl[nf][0] = Bsl[n][kb + (lane & 3)];
                bfl[nf][1] = Bsl[n][kb + (lane & 3) + 4];
            }
#pragma unroll
            for (int mf = 0; mf < 2; mf++)
#pragma unroll
                for (int nf = 0; nf < 4; nf++) {
                    mma_tf32(acc[mf][nf], afh[mf], bfl[nf]);
                    mma_tf32(acc[mf][nf], afl[mf], bfh[nf]);
                    mma_tf32(acc[mf][nf], afh[mf], bfh[nf]);
                }
        }
        __syncthreads();
    }

#pragma unroll
    for (int mf = 0; mf < 2; mf++) {
        const int r0 = bm + wm * 32 + mf * 16 + (lane >> 2);
#pragma unroll
        for (int nf = 0; nf < 4; nf++) {
            const int c0 = bn + wn * 32 + nf * 8 + 2 * (lane & 3);
            const float bv0 = bias ? bias[c0]     : 0.f;
            const float bv1 = bias ? bias[c0 + 1] : 0.f;
            float x0 = acc[mf][nf][0] + bv0, x1 = acc[mf][nf][1] + bv1;
            float x2 = acc[mf][nf][2] + bv0, x3 = acc[mf][nf][3] + bv1;
            if (RELU) { x0 = fmaxf(x0,0.f); x1 = fmaxf(x1,0.f);
                        x2 = fmaxf(x2,0.f); x3 = fmaxf(x3,0.f); }
            *(float2*)(C + (size_t)r0       * ldc + c0) = make_float2(x0, x1);
            *(float2*)(C + (size_t)(r0 + 8) * ldc + c0) = make_float2(x2, x3);
        }
    }
}

// ---------------- fused pairwise final kernel (tf32 tensor cores) ------------
// out[P, n] = relu(A[ti] - B[t*64+j] + rbias) @ rel_w2^T + rel_b2,
// P = ti*64 + j.  Block: 128 pairs (2 i's x 64 j) x 128 N-cols.

__global__ void __launch_bounds__(256, 2) final_tc(
    const float* __restrict__ Af,   // [NT, H]
    const float* __restrict__ Bf,   // [NT, H]
    const float* __restrict__ W2,   // rel_w2 [D, H]
    const float* __restrict__ hb,   // g_rbias [H]
    const float* __restrict__ b2,   // rel_b2 [D]
    float* __restrict__ out) {      // [NT*64, D]
    __shared__ unsigned Hs[128][36];
    __shared__ unsigned Ws[128][36];
    const int tid  = threadIdx.x;
    const int lane = tid & 31;
    const int warp = tid >> 5;
    const int wm   = warp >> 1;
    const int wn   = warp & 1;
    const int by   = blockIdx.y;           // pair block: pairs [by*128, by*128+128)
    const int bn   = blockIdx.x * 128;
    const int lp   = tid >> 1;             // 0..127 pair-row in tile
    const int lk   = (tid & 1) * 16;

    const int j       = lp & 63;
    const int i_local = lp >> 6;           // 0..1
    const int ti      = by * 2 + i_local;
    const int t       = ti >> 6;

    const float* arow = Af + (size_t)ti * H_;
    const float* brow = Bf + ((size_t)t * 64 + j) * H_;
    const float* wrow = W2 + (size_t)(bn + lp) * H_;

    float acc[2][8][4];
#pragma unroll
    for (int i = 0; i < 2; i++)
#pragma unroll
        for (int q = 0; q < 8; q++)
#pragma unroll
            for (int z = 0; z < 4; z++) acc[i][q][z] = 0.f;

    for (int k0 = 0; k0 < H_; k0 += 32) {
#pragma unroll
        for (int q = 0; q < 4; q++) {
            const int k  = k0 + lk + q * 4;
            const int kc = lk + q * 4;
            float4 a4 = *(const float4*)(arow + k);
            float4 b4 = *(const float4*)(brow + k);
            float4 c4 = *(const float4*)(hb + k);
            Hs[lp][kc+0] = f2tf(fmaxf(a4.x - b4.x + c4.x, 0.f));
            Hs[lp][kc+1] = f2tf(fmaxf(a4.y - b4.y + c4.y, 0.f));
            Hs[lp][kc+2] = f2tf(fmaxf(a4.z - b4.z + c4.z, 0.f));
            Hs[lp][kc+3] = f2tf(fmaxf(a4.w - b4.w + c4.w, 0.f));
            float4 w4 = *(const float4*)(wrow + k);
            Ws[lp][kc+0] = f2tf(w4.x); Ws[lp][kc+1] = f2tf(w4.y);
            Ws[lp][kc+2] = f2tf(w4.z); Ws[lp][kc+3] = f2tf(w4.w);
        }
        __syncthreads();
#pragma unroll
        for (int ks = 0; ks < 4; ks++) {
            const int kb = ks * 8;
            unsigned af[2][4], bf[8][2];
#pragma unroll
            for (int mf = 0; mf < 2; mf++) {
                const int r = wm * 32 + mf * 16 + (lane >> 2);
                af[mf][0] = Hs[r    ][kb + (lane & 3)];
                af[mf][1] = Hs[r + 8][kb + (lane & 3)];
                af[mf][2] = Hs[r    ][kb + (lane & 3) + 4];
                af[mf][3] = Hs[r + 8][kb + (lane & 3) + 4];
            }
#pragma unroll
            for (int nf = 0; nf < 8; nf++) {
                const int n = wn * 64 + nf * 8 + (lane >> 2);
                bf[nf][0] = Ws[n][kb + (lane & 3)];
                bf[nf][1] = Ws[n][kb + (lane & 3) + 4];
            }
#pragma unroll
            for (int mf = 0; mf < 2; mf++)
#pragma unroll
                for (int nf = 0; nf < 8; nf++)
                    mma_tf32(acc[mf][nf], af[mf], bf[nf]);
        }
        __syncthreads();
    }

#pragma unroll
    for (int mf = 0; mf < 2; mf++) {
        const int P0 = by * 128 + wm * 32 + mf * 16 + (lane >> 2);
#pragma unroll
        for (int nf = 0; nf < 8; nf++) {
            const int c0 = bn + wn * 64 + nf * 8 + 2 * (lane & 3);
            const float bv0 = b2[c0], bv1 = b2[c0 + 1];
            *(float2*)(out + (size_t)P0       * D_ + c0) =
                make_float2(acc[mf][nf][0] + bv0, acc[mf][nf][1] + bv1);
            *(float2*)(out + (size_t)(P0 + 8) * D_ + c0) =
                make_float2(acc[mf][nf][2] + bv0, acc[mf][nf][3] + bv1);
        }
    }
}

// ---------------- host orchestration ----------------------------------------

extern "C" void kernel_launch(void* const* d_in, const int* in_sizes, int n_in,
                              void* d_out, int out_size) {
    const float* roi      = (const float*)d_in[0];
    const float* spa      = (const float*)d_in[1];
    const float* subj_emb = (const float*)d_in[3];
    const float* obj_emb  = (const float*)d_in[4];
    const float* pred_emb = (const float*)d_in[5];
    const float* subj_w1  = (const float*)d_in[6];
    const float* subj_b1  = (const float*)d_in[7];
    const float* subj_w2  = (const float*)d_in[8];
    const float* subj_b2  = (const float*)d_in[9];
    const float* obj_w1   = (const float*)d_in[10];
    const float* obj_b1   = (const float*)d_in[11];
    const float* obj_w2   = (const float*)d_in[12];
    const float* obj_b2   = (const float*)d_in[13];
    const float* fuse_s_w1= (const float*)d_in[14];
    const float* fuse_s_b1= (const float*)d_in[15];
    const float* fuse_s_w2= (const float*)d_in[16];
    const float* fuse_s_b2= (const float*)d_in[17];
    const float* fuse_o_w1= (const float*)d_in[18];
    const float* fuse_o_b1= (const float*)d_in[19];
    const float* fuse_o_w2= (const float*)d_in[20];
    const float* fuse_o_b2= (const float*)d_in[21];
    const float* W_rs     = (const float*)d_in[22];
    const float* W_ro     = (const float*)d_in[23];
    const float* rel_w1   = (const float*)d_in[24];
    const float* rel_b1   = (const float*)d_in[25];
    const float* rel_w2   = (const float*)d_in[26];
    const float* rel_b2   = (const float*)d_in[27];
    float* out = (float*)d_out;

    float *pX, *ph1, *pfsb, *pfob, *pfs, *pfo, *pA, *pB;
    float *psb, *pob, *prb, *pws, *pwo, *pMs, *pMo;
    cudaGetSymbolAddress((void**)&pX,  g_X);
    cudaGetSymbolAddress((void**)&ph1, g_h1);
    cudaGetSymbolAddress((void**)&pfsb,g_fsb);
    cudaGetSymbolAddress((void**)&pfob,g_fob);
    cudaGetSymbolAddress((void**)&pfs, g_fs);
    cudaGetSymbolAddress((void**)&pfo, g_fo);
    cudaGetSymbolAddress((void**)&pA,  g_A);
    cudaGetSymbolAddress((void**)&pB,  g_Bm);
    cudaGetSymbolAddress((void**)&psb, g_sbias);
    cudaGetSymbolAddress((void**)&pob, g_obias);
    cudaGetSymbolAddress((void**)&prb, g_rbias);
    cudaGetSymbolAddress((void**)&pws, g_weffs);
    cudaGetSymbolAddress((void**)&pwo, g_weffo);
    cudaGetSymbolAddress((void**)&pMs, g_Ms);
    cudaGetSymbolAddress((void**)&pMo, g_Mo);

    concat_kernel<<<(NT_*INX_ + 255) / 256, 256>>>(roi, spa);
    prep_bias<<<2, 256>>>(subj_w1, subj_b1, obj_w1, obj_b1, rel_w1, rel_b1,
                          subj_emb, obj_emb, pred_emb);
    prep_weff<<<(H_*D_ + 255) / 256, 256>>>(fuse_s_w1, fuse_o_w1);
    prep_M<<<(H_*D_ + 255) / 256, 256>>>(rel_w1, W_rs, W_ro);

    const dim3 tblk(256);
    // subj branch L1 (tf32 TC): h1 = relu(X @ W1[:, :2052]^T + sbias)
    gemm_tc<1><<<dim3(H_/128, NT_/128), tblk>>>(NT_, H_, INX_, pX, INX_, subj_w1, INF_, psb, ph1, H_);
    gemm_tcx2<0><<<dim3(D_/64, NT_/128), tblk>>>(NT_, D_, H_, ph1, H_, subj_w2, H_, subj_b2, pfsb, D_);
    // obj branch
    gemm_tc<1><<<dim3(H_/128, NT_/128), tblk>>>(NT_, H_, INX_, pX, INX_, obj_w1, INF_, pob, ph1, H_);
    gemm_tcx2<0><<<dim3(D_/64, NT_/128), tblk>>>(NT_, D_, H_, ph1, H_, obj_w2, H_, obj_b2, pfob, D_);
    // fuse subj
    gemm_tcx2<1><<<dim3(H_/64, NT_/128), tblk>>>(NT_, H_, D_, pfsb, D_, pws, D_, fuse_s_b1, ph1, H_);
    gemm_tcx2<0><<<dim3(D_/64, NT_/128), tblk>>>(NT_, D_, H_, ph1, H_, fuse_s_w2, H_, fuse_s_b2, pfs, D_);
    // fuse obj
    gemm_tcx2<1><<<dim3(H_/64, NT_/128), tblk>>>(NT_, H_, D_, pfob, D_, pwo, D_, fuse_o_b1, ph1, H_);
    gemm_tcx2<0><<<dim3(D_/64, NT_/128), tblk>>>(NT_, D_, H_, ph1, H_, fuse_o_w2, H_, fuse_o_b2, pfo, D_);
    // projections folded with Wd
    gemm_tcx2<0><<<dim3(H_/64, NT_/128), tblk>>>(NT_, H_, D_, pfs, D_, pMs, D_, nullptr, pA, H_);
    gemm_tcx2<0><<<dim3(H_/64, NT_/128), tblk>>>(NT_, H_, D_, pfo, D_, pMo, D_, nullptr, pB, H_);
    // fused pairwise ReLU-GEMM epilogue (tf32 TC) -> 256 MB output
    final_tc<<<dim3(D_/128, NT_*64/128), tblk>>>(pA, pB, rel_w2, prb, rel_b2, out);
}

// round 4
// speedup vs baseline: 3.5714x; 1.1843x over previous
#include <cuda_runtime.h>
#include <cstddef>
#include <cstdint>

#define TN_ 64
#define MN_ 64
#define ROI_ 2048
#define SPA_ 4
#define WORD_ 300
#define INF_ 2352           // ROI+SPA+WORD (weight row stride)
#define INX_ 2052           // ROI+SPA (actual GEMM K)
#define H_ 512
#define D_ 256
#define LDR_ 556            // rel_w1 row stride (D+WORD)
#define NT_ (TN_*MN_)       // 4096 tokens

// ---------------- scratch (static device globals; no allocation) ------------
__device__ float g_X[NT_*INX_];       // concat(roi, spatial)
__device__ float g_h1[NT_*H_];        // shared hidden buffer (reused)
__device__ float g_fsb[NT_*D_];
__device__ float g_fob[NT_*D_];
__device__ float g_fs[NT_*D_];
__device__ float g_fo[NT_*D_];
__device__ float g_A[NT_*H_];         // fs @ (Wd W_rs)^T
__device__ float g_Bm[NT_*H_];        // fo @ (Wd W_ro)^T
__device__ float g_sbias[H_], g_obias[H_], g_rbias[H_];
__device__ float g_weffs[H_*D_], g_weffo[H_*D_];
__device__ float g_Ms[H_*D_], g_Mo[H_*D_];

// ---------------- helpers ----------------------------------------------------

__device__ __forceinline__ unsigned f2tf(float x) {
    unsigned u;
    asm("cvt.rna.tf32.f32 %0, %1;" : "=r"(u) : "f"(x));
    return u;
}

__device__ __forceinline__ void mma_tf32(float* d, const unsigned* a, const unsigned* b) {
    asm volatile(
        "mma.sync.aligned.m16n8k8.row.col.f32.tf32.tf32.f32 "
        "{%0,%1,%2,%3}, {%4,%5,%6,%7}, {%8,%9}, {%0,%1,%2,%3};\n"
        : "+f"(d[0]), "+f"(d[1]), "+f"(d[2]), "+f"(d[3])
        : "r"(a[0]), "r"(a[1]), "r"(a[2]), "r"(a[3]),
          "r"(b[0]), "r"(b[1]));
}

__device__ __forceinline__ void cpasync16(void* dst_smem, const void* src_gmem) {
    unsigned d = (unsigned)__cvta_generic_to_shared(dst_smem);
    asm volatile("cp.async.ca.shared.global [%0], [%1], 16;\n" :: "r"(d), "l"(src_gmem));
}
__device__ __forceinline__ void cp_commit() {
    asm volatile("cp.async.commit_group;\n");
}
template <int N>
__device__ __forceinline__ void cp_wait() {
    asm volatile("cp.async.wait_group %0;\n" :: "n"(N));
}

// ---------------- small prep kernels ---------------------------------------

__global__ void concat_kernel(const float* __restrict__ roi,
                              const float* __restrict__ spa) {
    int idx = blockIdx.x * blockDim.x + threadIdx.x;
    if (idx >= NT_ * INX_) return;
    int r = idx / INX_;
    int c = idx - r * INX_;
    g_X[idx] = (c < ROI_) ? roi[r * ROI_ + c] : spa[r * SPA_ + (c - ROI_)];
}

__global__ void prep_bias(const float* __restrict__ subj_w1, const float* __restrict__ subj_b1,
                          const float* __restrict__ obj_w1,  const float* __restrict__ obj_b1,
                          const float* __restrict__ rel_w1,  const float* __restrict__ rel_b1,
                          const float* __restrict__ subj_emb,
                          const float* __restrict__ obj_emb,
                          const float* __restrict__ pred_emb) {
    int h = blockIdx.x * blockDim.x + threadIdx.x;
    if (h >= H_) return;
    float s = subj_b1[h], o = obj_b1[h], r = rel_b1[h];
    const float* sw = subj_w1 + (size_t)h * INF_ + INX_;
    const float* ow = obj_w1  + (size_t)h * INF_ + INX_;
    const float* rw = rel_w1  + (size_t)h * LDR_ + D_;
    for (int w = 0; w < WORD_; w++) {
        s += sw[w] * subj_emb[w];
        o += ow[w] * obj_emb[w];
        r += rw[w] * pred_emb[w];
    }
    g_sbias[h] = s; g_obias[h] = o; g_rbias[h] = r;
}

__global__ void prep_weff(const float* __restrict__ fsw1,
                          const float* __restrict__ fow1) {
    int idx = blockIdx.x * blockDim.x + threadIdx.x;
    if (idx >= H_ * D_) return;
    int h = idx >> 8, k = idx & (D_ - 1);
    g_weffs[idx] = fsw1[h * (2*D_) + k] + fsw1[h * (2*D_) + D_ + k];
    g_weffo[idx] = fow1[h * (2*D_) + k] + fow1[h * (2*D_) + D_ + k];
}

__global__ void prep_M(const float* __restrict__ rel_w1,
                       const float* __restrict__ W_rs,
                       const float* __restrict__ W_ro) {
    int idx = blockIdx.x * blockDim.x + threadIdx.x;
    if (idx >= H_ * D_) return;
    int h = idx >> 8, k = idx & (D_ - 1);
    const float* wd = rel_w1 + (size_t)h * LDR_;
    float s = 0.f, o = 0.f;
    for (int d = 0; d < D_; d++) {
        float w = wd[d];
        s += w * W_rs[d * D_ + k];
        o += w * W_ro[d * D_ + k];
    }
    g_Ms[idx] = s; g_Mo[idx] = o;
}

// ---------------- pipelined tf32 TC GEMM: C = act(A[M,K]@B[N,K]^T + bias) ----
// 256 threads, block tile 128x128, BK=16, 2-stage cp.async double buffer.
// Warp tile 32x64 (2 mfrag x 8 nfrag).  M%128==0, N%128==0, K%4==0.

template <int RELU>
__global__ void __launch_bounds__(256, 2) gemm_tc2(
    int M, int N, int K,
    const float* __restrict__ A, int lda,
    const float* __restrict__ B, int ldb,
    const float* __restrict__ bias,
    float* __restrict__ C, int ldc) {
    __shared__ float As[2][128][20];
    __shared__ float Bs[2][128][20];
    const int tid  = threadIdx.x;
    const int lane = tid & 31;
    const int warp = tid >> 5;
    const int wm   = warp >> 1;
    const int wn   = warp & 1;
    const int bm   = blockIdx.y * 128;
    const int bn   = blockIdx.x * 128;
    const int ntiles = (K + 15) / 16;

    const int crow = tid >> 2;          // 0..63 base copy row
    const int cc4  = (tid & 3) * 4;     // 16B chunk col

    float acc[2][8][4];
#pragma unroll
    for (int i = 0; i < 2; i++)
#pragma unroll
        for (int j = 0; j < 8; j++)
#pragma unroll
            for (int q = 0; q < 4; q++) acc[i][j][q] = 0.f;

    auto issue = [&](int t) {
        const int s  = t & 1;
        const int k0 = t * 16;
        const int k  = k0 + cc4;
        const bool ok = k < K;
#pragma unroll
        for (int it = 0; it < 2; it++) {
            const int row = crow + it * 64;
            if (ok) {
                cpasync16(&As[s][row][cc4], A + (size_t)(bm + row) * lda + k);
                cpasync16(&Bs[s][row][cc4], B + (size_t)(bn + row) * ldb + k);
            } else {
                *(float4*)&As[s][row][cc4] = make_float4(0.f, 0.f, 0.f, 0.f);
                *(float4*)&Bs[s][row][cc4] = make_float4(0.f, 0.f, 0.f, 0.f);
            }
        }
        cp_commit();
    };

    issue(0);
    for (int t = 0; t < ntiles; t++) {
        const int s = t & 1;
        if (t + 1 < ntiles) { issue(t + 1); cp_wait<1>(); }
        else                { cp_wait<0>(); }
        __syncthreads();
#pragma unroll
        for (int ks = 0; ks < 2; ks++) {
            const int kb = ks * 8;
            const int c  = lane & 3;
            unsigned af[2][4], bf[8][2];
#pragma unroll
            for (int mf = 0; mf < 2; mf++) {
                const int r = wm * 32 + mf * 16 + (lane >> 2);
                af[mf][0] = f2tf(As[s][r    ][kb + c]);
                af[mf][1] = f2tf(As[s][r + 8][kb + c]);
                af[mf][2] = f2tf(As[s][r    ][kb + c + 4]);
                af[mf][3] = f2tf(As[s][r + 8][kb + c + 4]);
            }
#pragma unroll
            for (int nf = 0; nf < 8; nf++) {
                const int n = wn * 64 + nf * 8 + (lane >> 2);
                bf[nf][0] = f2tf(Bs[s][n][kb + c]);
                bf[nf][1] = f2tf(Bs[s][n][kb + c + 4]);
            }
#pragma unroll
            for (int mf = 0; mf < 2; mf++)
#pragma unroll
                for (int nf = 0; nf < 8; nf++)
                    mma_tf32(acc[mf][nf], af[mf], bf[nf]);
        }
        __syncthreads();
    }

#pragma unroll
    for (int mf = 0; mf < 2; mf++) {
        const int r0 = bm + wm * 32 + mf * 16 + (lane >> 2);
#pragma unroll
        for (int nf = 0; nf < 8; nf++) {
            const int c0 = bn + wn * 64 + nf * 8 + 2 * (lane & 3);
            const float bv0 = bias ? bias[c0]     : 0.f;
            const float bv1 = bias ? bias[c0 + 1] : 0.f;
            float x0 = acc[mf][nf][0] + bv0, x1 = acc[mf][nf][1] + bv1;
            float x2 = acc[mf][nf][2] + bv0, x3 = acc[mf][nf][3] + bv1;
            if (RELU) { x0 = fmaxf(x0,0.f); x1 = fmaxf(x1,0.f);
                        x2 = fmaxf(x2,0.f); x3 = fmaxf(x3,0.f); }
            *(float2*)(C + (size_t)r0       * ldc + c0) = make_float2(x0, x1);
            *(float2*)(C + (size_t)(r0 + 8) * ldc + c0) = make_float2(x2, x3);
        }
    }
}

// ---------------- tf32x2 split-precision TC GEMM (near-fp32 accuracy) --------

template <int RELU>
__global__ void __launch_bounds__(256, 2) gemm_tcx2(
    int M, int N, int K,
    const float* __restrict__ A, int lda,
    const float* __restrict__ B, int ldb,
    const float* __restrict__ bias,
    float* __restrict__ C, int ldc) {
    __shared__ unsigned Ash[128][20], Asl[128][20];
    __shared__ unsigned Bsh[64][20],  Bsl[64][20];
    const int tid  = threadIdx.x;
    const int lane = tid & 31;
    const int warp = tid >> 5;
    const int wm   = warp >> 1;
    const int wn   = warp & 1;
    const int bm   = blockIdx.y * 128;
    const int bn   = blockIdx.x * 64;
    const int la   = tid >> 1;
    const int lak  = (tid & 1) * 8;
    const int lb   = tid >> 2;
    const int lbk  = (tid & 3) * 4;

    const float* arow = A + (size_t)(bm + la) * lda;
    const float* brow = B + (size_t)(bn + lb) * ldb;

    float acc[2][4][4];
#pragma unroll
    for (int i = 0; i < 2; i++)
#pragma unroll
        for (int j = 0; j < 4; j++)
#pragma unroll
            for (int q = 0; q < 4; q++) acc[i][j][q] = 0.f;

    for (int k0 = 0; k0 < K; k0 += 16) {
#pragma unroll
        for (int q = 0; q < 2; q++) {
            float4 a4 = *(const float4*)(arow + k0 + lak + q * 4);
            const int kc = lak + q * 4;
            float av[4] = {a4.x, a4.y, a4.z, a4.w};
#pragma unroll
            for (int c = 0; c < 4; c++) {
                unsigned hi = f2tf(av[c]);
                Ash[la][kc + c] = hi;
                Asl[la][kc + c] = f2tf(av[c] - __uint_as_float(hi));
            }
        }
        {
            float4 b4 = *(const float4*)(brow + k0 + lbk);
            float bv[4] = {b4.x, b4.y, b4.z, b4.w};
#pragma unroll
            for (int c = 0; c < 4; c++) {
                unsigned hi = f2tf(bv[c]);
                Bsh[lb][lbk + c] = hi;
                Bsl[lb][lbk + c] = f2tf(bv[c] - __uint_as_float(hi));
            }
        }
        __syncthreads();
#pragma unroll
        for (int ks = 0; ks < 2; ks++) {
            const int kb = ks * 8;
            unsigned afh[2][4], afl[2][4], bfh[4][2], bfl[4][2];
#pragma unroll
            for (int mf = 0; mf < 2; mf++) {
                const int r = wm * 32 + mf * 16 + (lane >> 2);
                afh[mf][0] = Ash[r    ][kb + (lane & 3)];
                afh[mf][1] = Ash[r + 8][kb + (lane & 3)];
                afh[mf][2] = Ash[r    ][kb + (lane & 3) + 4];
                afh[mf][3] = Ash[r + 8][kb + (lane & 3) + 4];
                afl[mf][0] = Asl[r    ][kb + (lane & 3)];
                afl[mf][1] = Asl[r + 8][kb + (lane & 3)];
                afl[mf][2] = Asl[r    ][kb + (lane & 3) + 4];
                afl[mf][3] = Asl[r + 8][kb + (lane & 3) + 4];
            }
#pragma unroll
            for (int nf = 0; nf < 4; nf++) {
                const int n = wn * 32 + nf * 8 + (lane >> 2);
                bfh[nf][0] = Bsh[n][kb + (lane & 3)];
                bfh[nf][1] = Bsh[n][kb + (lane & 3) + 4];
                bfl[nf][0] = Bsl[n][kb + (lane & 3)];
                bfl[nf][1] = Bsl[n][kb + (lane & 3) + 4];
            }
#pragma unroll
            for (int mf = 0; mf < 2; mf++)
#pragma unroll
                for (int nf = 0; nf < 4; nf++) {
                    mma_tf32(acc[mf][nf], afh[mf], bfl[nf]);
                    mma_tf32(acc[mf][nf], afl[mf], bfh[nf]);
                    mma_tf32(acc[mf][nf], afh[mf], bfh[nf]);
                }
        }
        __syncthreads();
    }

#pragma unroll
    for (int mf = 0; mf < 2; mf++) {
        const int r0 = bm + wm * 32 + mf * 16 + (lane >> 2);
#pragma unroll
        for (int nf = 0; nf < 4; nf++) {
            const int c0 = bn + wn * 32 + nf * 8 + 2 * (lane & 3);
            const float bv0 = bias ? bias[c0]     : 0.f;
            const float bv1 = bias ? bias[c0 + 1] : 0.f;
            float x0 = acc[mf][nf][0] + bv0, x1 = acc[mf][nf][1] + bv1;
            float x2 = acc[mf][nf][2] + bv0, x3 = acc[mf][nf][3] + bv1;
            if (RELU) { x0 = fmaxf(x0,0.f); x1 = fmaxf(x1,0.f);
                        x2 = fmaxf(x2,0.f); x3 = fmaxf(x3,0.f); }
            *(float2*)(C + (size_t)r0       * ldc + c0) = make_float2(x0, x1);
            *(float2*)(C + (size_t)(r0 + 8) * ldc + c0) = make_float2(x2, x3);
        }
    }
}

// ---------------- pipelined fused pairwise final kernel ----------------------
// out[P, n] = relu((A[ti]+rbias) - B[t*64+j]) @ rel_w2^T + rel_b2,
// P = ti*64 + j.  Block: 128 pairs (2 i x 64 j) x 128 N-cols.  BK=16, 2 stages.

__global__ void __launch_bounds__(256, 2) final_tc2(
    const float* __restrict__ Af,   // [NT, H]
    const float* __restrict__ Bf,   // [NT, H]
    const float* __restrict__ W2,   // rel_w2 [D, H]
    const float* __restrict__ hb,   // g_rbias [H]
    const float* __restrict__ b2,   // rel_b2 [D]
    float* __restrict__ out) {      // [NT*64, D]
    __shared__ float ACs[2][H_];
    __shared__ float Bs[2][64][20];
    __shared__ float Ws[2][128][20];
    const int tid  = threadIdx.x;
    const int lane = tid & 31;
    const int warp = tid >> 5;
    const int wm   = warp >> 1;
    const int wn   = warp & 1;
    const int by   = blockIdx.y;            // pairs [by*128, by*128+128)
    const int bn   = blockIdx.x * 128;
    const int ti0  = by * 2;
    const int tt   = ti0 >> 6;              // frame index (same for ti0, ti0+1)
    const float* bbase = Bf + (size_t)tt * 64 * H_;

    // preload ac[i][k] = Af[ti0+i][k] + rbias[k]
    {
        const int i = tid >> 7;
        const int k = (tid & 127) * 4;
        float4 a = *(const float4*)(Af + (size_t)(ti0 + i) * H_ + k);
        float4 c = *(const float4*)(hb + k);
        *(float4*)&ACs[i][k] = make_float4(a.x + c.x, a.y + c.y, a.z + c.z, a.w + c.w);
    }

    const int crow = tid >> 2;
    const int cc4  = (tid & 3) * 4;

    float acc[2][8][4];
#pragma unroll
    for (int i = 0; i < 2; i++)
#pragma unroll
        for (int j = 0; j < 8; j++)
#pragma unroll
            for (int q = 0; q < 4; q++) acc[i][j][q] = 0.f;

    auto issue = [&](int t) {
        const int s  = t & 1;
        const int k0 = t * 16 + cc4;
        if (crow < 64)
            cpasync16(&Bs[s][crow][cc4], bbase + (size_t)crow * H_ + k0);
#pragma unroll
        for (int it = 0; it < 2; it++) {
            const int row = crow + it * 64;
            cpasync16(&Ws[s][row][cc4], W2 + (size_t)(bn + row) * H_ + k0);
        }
        cp_commit();
    };

    const int NTILES = H_ / 16;   // 32
    issue(0);
    for (int t = 0; t < NTILES; t++) {
        const int s = t & 1;
        if (t + 1 < NTILES) { issue(t + 1); cp_wait<1>(); }
        else                { cp_wait<0>(); }
        __syncthreads();
#pragma unroll
        for (int ks = 0; ks < 2; ks++) {
            const int kb = ks * 8;
            const int c  = lane & 3;
            const int kg = t * 16 + kb + c;
            unsigned af[2][4], bf[8][2];
#pragma unroll
            for (int mf = 0; mf < 2; mf++) {
                const int r  = wm * 32 + mf * 16 + (lane >> 2);
                const int i  = r >> 6;
                const int j  = r & 63;
                const float ac0 = ACs[i][kg];
                const float ac1 = ACs[i][kg + 4];
                af[mf][0] = f2tf(fmaxf(ac0 - Bs[s][j    ][kb + c],     0.f));
                af[mf][1] = f2tf(fmaxf(ac0 - Bs[s][j + 8][kb + c],     0.f));
                af[mf][2] = f2tf(fmaxf(ac1 - Bs[s][j    ][kb + c + 4], 0.f));
                af[mf][3] = f2tf(fmaxf(ac1 - Bs[s][j + 8][kb + c + 4], 0.f));
            }
#pragma unroll
            for (int nf = 0; nf < 8; nf++) {
                const int n = wn * 64 + nf * 8 + (lane >> 2);
                bf[nf][0] = f2tf(Ws[s][n][kb + c]);
                bf[nf][1] = f2tf(Ws[s][n][kb + c + 4]);
            }
#pragma unroll
            for (int mf = 0; mf < 2; mf++)
#pragma unroll
                for (int nf = 0; nf < 8; nf++)
                    mma_tf32(acc[mf][nf], af[mf], bf[nf]);
        }
        __syncthreads();
    }

#pragma unroll
    for (int mf = 0; mf < 2; mf++) {
        const int P0 = by * 128 + wm * 32 + mf * 16 + (lane >> 2);
#pragma unroll
        for (int nf = 0; nf < 8; nf++) {
            const int c0 = bn + wn * 64 + nf * 8 + 2 * (lane & 3);
            const float bv0 = b2[c0], bv1 = b2[c0 + 1];
            *(float2*)(out + (size_t)P0       * D_ + c0) =
                make_float2(acc[mf][nf][0] + bv0, acc[mf][nf][1] + bv1);
            *(float2*)(out + (size_t)(P0 + 8) * D_ + c0) =
                make_float2(acc[mf][nf][2] + bv0, acc[mf][nf][3] + bv1);
        }
    }
}

// ---------------- host orchestration ----------------------------------------

extern "C" void kernel_launch(void* const* d_in, const int* in_sizes, int n_in,
                              void* d_out, int out_size) {
    const float* roi      = (const float*)d_in[0];
    const float* spa      = (const float*)d_in[1];
    const float* subj_emb = (const float*)d_in[3];
    const float* obj_emb  = (const float*)d_in[4];
    const float* pred_emb = (const float*)d_in[5];
    const float* subj_w1  = (const float*)d_in[6];
    const float* subj_b1  = (const float*)d_in[7];
    const float* subj_w2  = (const float*)d_in[8];
    const float* subj_b2  = (const float*)d_in[9];
    const float* obj_w1   = (const float*)d_in[10];
    const float* obj_b1   = (const float*)d_in[11];
    const float* obj_w2   = (const float*)d_in[12];
    const float* obj_b2   = (const float*)d_in[13];
    const float* fuse_s_w1= (const float*)d_in[14];
    const float* fuse_s_b1= (const float*)d_in[15];
    const float* fuse_s_w2= (const float*)d_in[16];
    const float* fuse_s_b2= (const float*)d_in[17];
    const float* fuse_o_w1= (const float*)d_in[18];
    const float* fuse_o_b1= (const float*)d_in[19];
    const float* fuse_o_w2= (const float*)d_in[20];
    const float* fuse_o_b2= (const float*)d_in[21];
    const float* W_rs     = (const float*)d_in[22];
    const float* W_ro     = (const float*)d_in[23];
    const float* rel_w1   = (const float*)d_in[24];
    const float* rel_b1   = (const float*)d_in[25];
    const float* rel_w2   = (const float*)d_in[26];
    const float* rel_b2   = (const float*)d_in[27];
    float* out = (float*)d_out;

    float *pX, *ph1, *pfsb, *pfob, *pfs, *pfo, *pA, *pB;
    float *psb, *pob, *prb, *pws, *pwo, *pMs, *pMo;
    cudaGetSymbolAddress((void**)&pX,  g_X);
    cudaGetSymbolAddress((void**)&ph1, g_h1);
    cudaGetSymbolAddress((void**)&pfsb,g_fsb);
    cudaGetSymbolAddress((void**)&pfob,g_fob);
    cudaGetSymbolAddress((void**)&pfs, g_fs);
    cudaGetSymbolAddress((void**)&pfo, g_fo);
    cudaGetSymbolAddress((void**)&pA,  g_A);
    cudaGetSymbolAddress((void**)&pB,  g_Bm);
    cudaGetSymbolAddress((void**)&psb, g_sbias);
    cudaGetSymbolAddress((void**)&pob, g_obias);
    cudaGetSymbolAddress((void**)&prb, g_rbias);
    cudaGetSymbolAddress((void**)&pws, g_weffs);
    cudaGetSymbolAddress((void**)&pwo, g_weffo);
    cudaGetSymbolAddress((void**)&pMs, g_Ms);
    cudaGetSymbolAddress((void**)&pMo, g_Mo);

    concat_kernel<<<(NT_*INX_ + 255) / 256, 256>>>(roi, spa);
    prep_bias<<<2, 256>>>(subj_w1, subj_b1, obj_w1, obj_b1, rel_w1, rel_b1,
                          subj_emb, obj_emb, pred_emb);
    prep_weff<<<(H_*D_ + 255) / 256, 256>>>(fuse_s_w1, fuse_o_w1);
    prep_M<<<(H_*D_ + 255) / 256, 256>>>(rel_w1, W_rs, W_ro);

    const dim3 tblk(256);
    // subj branch L1 (pipelined tf32 TC): h1 = relu(X @ W1[:, :2052]^T + sbias)
    gemm_tc2<1><<<dim3(H_/128, NT_/128), tblk>>>(NT_, H_, INX_, pX, INX_, subj_w1, INF_, psb, ph1, H_);
    gemm_tcx2<0><<<dim3(D_/64, NT_/128), tblk>>>(NT_, D_, H_, ph1, H_, subj_w2, H_, subj_b2, pfsb, D_);
    // obj branch
    gemm_tc2<1><<<dim3(H_/128, NT_/128), tblk>>>(NT_, H_, INX_, pX, INX_, obj_w1, INF_, pob, ph1, H_);
    gemm_tcx2<0><<<dim3(D_/64, NT_/128), tblk>>>(NT_, D_, H_, ph1, H_, obj_w2, H_, obj_b2, pfob, D_);
    // fuse subj
    gemm_tcx2<1><<<dim3(H_/64, NT_/128), tblk>>>(NT_, H_, D_, pfsb, D_, pws, D_, fuse_s_b1, ph1, H_);
    gemm_tcx2<0><<<dim3(D_/64, NT_/128), tblk>>>(NT_, D_, H_, ph1, H_, fuse_s_w2, H_, fuse_s_b2, pfs, D_);
    // fuse obj
    gemm_tcx2<1><<<dim3(H_/64, NT_/128), tblk>>>(NT_, H_, D_, pfob, D_, pwo, D_, fuse_o_b1, ph1, H_);
    gemm_tcx2<0><<<dim3(D_/64, NT_/128), tblk>>>(NT_, D_, H_, ph1, H_, fuse_o_w2, H_, fuse_o_b2, pfo, D_);
    // projections folded with Wd
    gemm_tcx2<0><<<dim3(H_/64, NT_/128), tblk>>>(NT_, H_, D_, pfs, D_, pMs, D_, nullptr, pA, H_);
    gemm_tcx2<0><<<dim3(H_/64, NT_/128), tblk>>>(NT_, H_, D_, pfo, D_, pMo, D_, nullptr, pB, H_);
    // fused pairwise ReLU-GEMM epilogue (pipelined tf32 TC) -> 256 MB output
    final_tc2<<<dim3(D_/128, NT_*64/128), tblk>>>(pA, pB, rel_w2, prb, rel_b2, out);
}